// round 3
// baseline (speedup 1.0000x reference)
#include <cuda_runtime.h>

// ----------------------------------------------------------------------------
// Clebsch-Gordan sparse product, LMAX=5, TAU=32, BATCH=32.
// R3: one block per (l,l1,l2) tuple (111 cases), tuple index FASTEST in
// blockIdx so waves are mixed and heavy work doesn't cluster in a sparse tail.
// Per-case code is small (runtime iter loop, single output L) -> fits I$.
// CG coefficients are constexpr -> FFMA immediates. Output staged through
// shared memory per warp for coalesced float4 stores.
// ----------------------------------------------------------------------------

#define LMAXV 5
#define ROWF  1579008            // output floats per batch row
#define NTUP  111
#define NBLOCKS (32*4*NTUP)      // b(32) * quarter(4) * tuple(111), tuple fastest

// ---------------- constexpr CG machinery (compile-time only) ----------------

__host__ __device__ constexpr double cfact(int n) {
    double r = 1.0;
    for (int i = 2; i <= n; ++i) r *= (double)i;
    return r;
}

__host__ __device__ constexpr double csqrt_(double x) {
    if (x <= 0.0) return 0.0;
    double g = (x >= 1.0) ? x : 1.0;
    for (int i = 0; i < 160; ++i) g = 0.5 * (g + x / g);
    return g;
}

__host__ __device__ constexpr double cg_coef(int j1, int m1, int j2, int m2, int j3, int m3) {
    if (m1 + m2 != m3) return 0.0;
    if (m1 < -j1 || m1 > j1 || m2 < -j2 || m2 > j2 || m3 < -j3 || m3 > j3) return 0.0;
    int lo = (j1 > j2) ? (j1 - j2) : (j2 - j1);
    if (j3 < lo || j3 > j1 + j2) return 0.0;
    double pref = csqrt_((2.0 * j3 + 1.0) * cfact(j3 + j1 - j2) * cfact(j3 - j1 + j2)
                         * cfact(j1 + j2 - j3) / cfact(j1 + j2 + j3 + 1));
    pref = pref * csqrt_(cfact(j3 + m3) * cfact(j3 - m3) * cfact(j1 - m1) * cfact(j1 + m1)
                         * cfact(j2 - m2) * cfact(j2 + m2));
    double s = 0.0;
    for (int k = 0; k <= j1 + j2 - j3; ++k) {
        int a2 = j1 + j2 - j3 - k;
        int a3 = j1 - m1 - k;
        int a4 = j2 + m2 - k;
        int a5 = j3 - j2 + m1 + k;
        int a6 = j3 - j1 - m2 + k;
        if (a2 < 0 || a3 < 0 || a4 < 0 || a5 < 0 || a6 < 0) continue;
        double den = cfact(k) * cfact(a2) * cfact(a3) * cfact(a4) * cfact(a5) * cfact(a6);
        s += ((k & 1) ? -1.0 : 1.0) / den;
    }
    return pref * s;
}

// output base (in floats, within one batch row) of tuple (L, L1, L2);
// enumeration: l outer, then l1, then l2 (reference LTUPLES order)
__host__ __device__ constexpr int out_base_f(int L1, int L2, int L) {
    int off = 0;
    for (int l = 0; l <= LMAXV; ++l)
        for (int l1 = 0; l1 <= LMAXV; ++l1)
            for (int l2 = 0; l2 <= LMAXV; ++l2) {
                int lo = (l1 > l2) ? (l1 - l2) : (l2 - l1);
                if (!(lo <= l && l <= l1 + l2)) continue;
                if (l == L && l1 == L1 && l2 == L2) return off;
                off += 1024 * (2 * l + 1) * 2;
            }
    return 0;
}

// ---------------- per-L unrolled accumulation (identical to R2) ----------------

template <int L1, int L2, int L, int M, int M1, int HI1>
__device__ __forceinline__ void sum_m1(const float2* A, const float2* Bv,
                                       float& accr, float& acci) {
    if constexpr (M1 <= HI1) {
        constexpr double cd = cg_coef(L1, M1, L2, M - M1, L, M);
        if constexpr (cd != 0.0) {
            constexpr float c = (float)cd;
            float ar = A[M1 + L1].x,      ai = A[M1 + L1].y;
            float br = Bv[M - M1 + L2].x, bi = Bv[M - M1 + L2].y;
            float pr = fmaf(ar, br, -(ai * bi));
            float pi = fmaf(ar, bi, ai * br);
            accr = fmaf(c, pr, accr);
            acci = fmaf(c, pi, acci);
        }
        sum_m1<L1, L2, L, M, M1 + 1, HI1>(A, Bv, accr, acci);
    }
}

template <int L1, int L2, int L, int M>
__device__ __forceinline__ void per_m(const float2* A, const float2* Bv, float2* acc) {
    if constexpr (M <= L) {
        constexpr int LO1 = (-L1 > M - L2) ? -L1 : (M - L2);
        constexpr int HI1 = (L1 < M + L2) ? L1 : (M + L2);
        float r = 0.f, i = 0.f;
        sum_m1<L1, L2, L, M, LO1, HI1>(A, Bv, r, i);
        acc[M + L] = make_float2(r, i);
        per_m<L1, L2, L, M + 1>(A, Bv, acc);
    }
}

// ---------------- per-tuple block body ----------------

template <int L1, int L2, int L>
__device__ __forceinline__ void tuple_work(const float* __restrict__ fs,
                                           float* __restrict__ out,
                                           float* s1, float* s2, float* stage,
                                           int q, int b) {
    const int tid = threadIdx.x;
    const int warp = tid >> 5;
    const int lane = tid & 31;
    constexpr int TW = 2 * L + 1;

    // stage input fragments (each is 32*(2l+1) float2, contiguous in gmem)
    {
        const float4* i1 = (const float4*)(fs + (size_t)b * 2304 + 64 * L1 * L1);
        const float4* i2 = (const float4*)(fs + (size_t)b * 2304 + 64 * L2 * L2);
        constexpr int N1 = 16 * (2 * L1 + 1);
        constexpr int N2 = 16 * (2 * L2 + 1);
        for (int j = tid; j < N1; j += 128) ((float4*)s1)[j] = i1[j];
        for (int j = tid; j < N2; j += 128) ((float4*)s2)[j] = i2[j];
    }
    __syncthreads();

    // Bv depends only on lane (t2): load once
    float2 Bv[2 * L2 + 1];
    {
        const float2* bv = (const float2*)s2 + lane * (2 * L2 + 1);
#pragma unroll
        for (int i = 0; i < 2 * L2 + 1; ++i) Bv[i] = bv[i];
    }

    float* outb = out + (size_t)b * ROWF;
    float* wstage = stage + warp * 704;
    constexpr int OB = out_base_f(L1, L2, L);

#pragma unroll 1
    for (int iter = 0; iter < 2; ++iter) {
        const int t1 = q * 8 + iter * 4 + warp;

        float2 A[2 * L1 + 1];
        {
            const float2* av = (const float2*)s1 + t1 * (2 * L1 + 1);
#pragma unroll
            for (int i = 0; i < 2 * L1 + 1; ++i) A[i] = av[i];
        }

        float2 acc[TW];
        per_m<L1, L2, L, -L>(A, Bv, acc);

        // stage: lane t2 owns TW float2s, layout = exact gmem tile layout
        float2* st2 = (float2*)wstage;
#pragma unroll
        for (int m = 0; m < TW; ++m) st2[lane * TW + m] = acc[m];
        __syncwarp();

        float4* g4 = (float4*)(outb + OB + t1 * 32 * 2 * TW);
        const float4* s4 = (const float4*)wstage;
        constexpr int N4 = 16 * TW;   // 32 lanes * TW * 2 floats / 4
        for (int j = lane; j < N4; j += 32) g4[j] = s4[j];
        __syncwarp();
    }
}

// ---------------- kernel ----------------

__global__ void __launch_bounds__(128, 6)
cg_sparse_kernel(const float* __restrict__ fs, float* __restrict__ out) {
    __shared__ __align__(16) float s1[704];
    __shared__ __align__(16) float s2[704];
    __shared__ __align__(16) float stage[4 * 704];

    const int bx = blockIdx.x;
    const int t = bx % NTUP;         // tuple index: FASTEST -> mixed waves
    const int r = bx / NTUP;
    const int q = r & 3;
    const int b = r >> 2;

#define TCASE(I, L_, A_, B_) case I: tuple_work<A_, B_, L_>(fs, out, s1, s2, stage, q, b); break;
    switch (t) {
        // l = 0
        TCASE(0,0,0,0) TCASE(1,0,1,1) TCASE(2,0,2,2) TCASE(3,0,3,3) TCASE(4,0,4,4) TCASE(5,0,5,5)
        // l = 1
        TCASE(6,1,0,1) TCASE(7,1,1,0) TCASE(8,1,1,1) TCASE(9,1,1,2) TCASE(10,1,2,1)
        TCASE(11,1,2,2) TCASE(12,1,2,3) TCASE(13,1,3,2) TCASE(14,1,3,3) TCASE(15,1,3,4)
        TCASE(16,1,4,3) TCASE(17,1,4,4) TCASE(18,1,4,5) TCASE(19,1,5,4) TCASE(20,1,5,5)
        // l = 2
        TCASE(21,2,0,2) TCASE(22,2,1,1) TCASE(23,2,1,2) TCASE(24,2,1,3) TCASE(25,2,2,0)
        TCASE(26,2,2,1) TCASE(27,2,2,2) TCASE(28,2,2,3) TCASE(29,2,2,4) TCASE(30,2,3,1)
        TCASE(31,2,3,2) TCASE(32,2,3,3) TCASE(33,2,3,4) TCASE(34,2,3,5) TCASE(35,2,4,2)
        TCASE(36,2,4,3) TCASE(37,2,4,4) TCASE(38,2,4,5) TCASE(39,2,5,3) TCASE(40,2,5,4)
        TCASE(41,2,5,5)
        // l = 3
        TCASE(42,3,0,3) TCASE(43,3,1,2) TCASE(44,3,1,3) TCASE(45,3,1,4) TCASE(46,3,2,1)
        TCASE(47,3,2,2) TCASE(48,3,2,3) TCASE(49,3,2,4) TCASE(50,3,2,5) TCASE(51,3,3,0)
        TCASE(52,3,3,1) TCASE(53,3,3,2) TCASE(54,3,3,3) TCASE(55,3,3,4) TCASE(56,3,3,5)
        TCASE(57,3,4,1) TCASE(58,3,4,2) TCASE(59,3,4,3) TCASE(60,3,4,4) TCASE(61,3,4,5)
        TCASE(62,3,5,2) TCASE(63,3,5,3) TCASE(64,3,5,4) TCASE(65,3,5,5)
        // l = 4
        TCASE(66,4,0,4) TCASE(67,4,1,3) TCASE(68,4,1,4) TCASE(69,4,1,5) TCASE(70,4,2,2)
        TCASE(71,4,2,3) TCASE(72,4,2,4) TCASE(73,4,2,5) TCASE(74,4,3,1) TCASE(75,4,3,2)
        TCASE(76,4,3,3) TCASE(77,4,3,4) TCASE(78,4,3,5) TCASE(79,4,4,0) TCASE(80,4,4,1)
        TCASE(81,4,4,2) TCASE(82,4,4,3) TCASE(83,4,4,4) TCASE(84,4,4,5) TCASE(85,4,5,1)
        TCASE(86,4,5,2) TCASE(87,4,5,3) TCASE(88,4,5,4) TCASE(89,4,5,5)
        // l = 5
        TCASE(90,5,0,5) TCASE(91,5,1,4) TCASE(92,5,1,5) TCASE(93,5,2,3) TCASE(94,5,2,4)
        TCASE(95,5,2,5) TCASE(96,5,3,2) TCASE(97,5,3,3) TCASE(98,5,3,4) TCASE(99,5,3,5)
        TCASE(100,5,4,1) TCASE(101,5,4,2) TCASE(102,5,4,3) TCASE(103,5,4,4) TCASE(104,5,4,5)
        TCASE(105,5,5,0) TCASE(106,5,5,1) TCASE(107,5,5,2) TCASE(108,5,5,3) TCASE(109,5,5,4)
        TCASE(110,5,5,5)
        default: break;
    }
#undef TCASE
}

extern "C" void kernel_launch(void* const* d_in, const int* in_sizes, int n_in,
                              void* d_out, int out_size) {
    const float* fs = (const float*)d_in[0];
    float* out = (float*)d_out;
    cg_sparse_kernel<<<NBLOCKS, 128>>>(fs, out);
}

// round 5
// speedup vs baseline: 2.2860x; 2.2860x over previous
#include <cuda_runtime.h>

// ----------------------------------------------------------------------------
// Clebsch-Gordan sparse product, LMAX=5, TAU=32, BATCH=32.
// R5 = R4 resubmitted (previous round was an infra failure, container died).
// R4 = R2 (pair-grouped blocks, per-output-L recompute, staged coalesced
// stores) + HEAVY-FIRST pair scheduling: the 36 (l1,l2) pairs are launched in
// descending cost order so the drain tail consists of the lightest blocks.
// ----------------------------------------------------------------------------

#define LMAXV 5
#define ROWF  1579008            // output floats per batch row
#define NBLOCKS (36*32*4)        // pair(36, slowest) * b(32) * quarter(4)

// ---------------- constexpr CG machinery (compile-time only) ----------------

__host__ __device__ constexpr double cfact(int n) {
    double r = 1.0;
    for (int i = 2; i <= n; ++i) r *= (double)i;
    return r;
}

__host__ __device__ constexpr double csqrt_(double x) {
    if (x <= 0.0) return 0.0;
    double g = (x >= 1.0) ? x : 1.0;
    for (int i = 0; i < 160; ++i) g = 0.5 * (g + x / g);
    return g;
}

__host__ __device__ constexpr double cg_coef(int j1, int m1, int j2, int m2, int j3, int m3) {
    if (m1 + m2 != m3) return 0.0;
    if (m1 < -j1 || m1 > j1 || m2 < -j2 || m2 > j2 || m3 < -j3 || m3 > j3) return 0.0;
    int lo = (j1 > j2) ? (j1 - j2) : (j2 - j1);
    if (j3 < lo || j3 > j1 + j2) return 0.0;
    double pref = csqrt_((2.0 * j3 + 1.0) * cfact(j3 + j1 - j2) * cfact(j3 - j1 + j2)
                         * cfact(j1 + j2 - j3) / cfact(j1 + j2 + j3 + 1));
    pref = pref * csqrt_(cfact(j3 + m3) * cfact(j3 - m3) * cfact(j1 - m1) * cfact(j1 + m1)
                         * cfact(j2 - m2) * cfact(j2 + m2));
    double s = 0.0;
    for (int k = 0; k <= j1 + j2 - j3; ++k) {
        int a2 = j1 + j2 - j3 - k;
        int a3 = j1 - m1 - k;
        int a4 = j2 + m2 - k;
        int a5 = j3 - j2 + m1 + k;
        int a6 = j3 - j1 - m2 + k;
        if (a2 < 0 || a3 < 0 || a4 < 0 || a5 < 0 || a6 < 0) continue;
        double den = cfact(k) * cfact(a2) * cfact(a3) * cfact(a4) * cfact(a5) * cfact(a6);
        s += ((k & 1) ? -1.0 : 1.0) / den;
    }
    return pref * s;
}

// output base (in floats, within one batch row) of tuple (L, L1, L2);
// enumeration: l outer, then l1, then l2 (reference LTUPLES order)
__host__ __device__ constexpr int out_base_f(int L1, int L2, int L) {
    int off = 0;
    for (int l = 0; l <= LMAXV; ++l)
        for (int l1 = 0; l1 <= LMAXV; ++l1)
            for (int l2 = 0; l2 <= LMAXV; ++l2) {
                int lo = (l1 > l2) ? (l1 - l2) : (l2 - l1);
                if (!(lo <= l && l <= l1 + l2)) continue;
                if (l == L && l1 == L1 && l2 == L2) return off;
                off += 1024 * (2 * l + 1) * 2;
            }
    return 0;
}

// ---------------- per-L unrolled accumulation (identical to R2) ----------------

template <int L1, int L2, int L, int M, int M1, int HI1>
__device__ __forceinline__ void sum_m1(const float2* A, const float2* Bv,
                                       float& accr, float& acci) {
    if constexpr (M1 <= HI1) {
        constexpr double cd = cg_coef(L1, M1, L2, M - M1, L, M);
        if constexpr (cd != 0.0) {
            constexpr float c = (float)cd;
            float ar = A[M1 + L1].x,      ai = A[M1 + L1].y;
            float br = Bv[M - M1 + L2].x, bi = Bv[M - M1 + L2].y;
            float pr = fmaf(ar, br, -(ai * bi));
            float pi = fmaf(ar, bi, ai * br);
            accr = fmaf(c, pr, accr);
            acci = fmaf(c, pi, acci);
        }
        sum_m1<L1, L2, L, M, M1 + 1, HI1>(A, Bv, accr, acci);
    }
}

template <int L1, int L2, int L, int M>
__device__ __forceinline__ void per_m(const float2* A, const float2* Bv, float2* acc) {
    if constexpr (M <= L) {
        constexpr int LO1 = (-L1 > M - L2) ? -L1 : (M - L2);
        constexpr int HI1 = (L1 < M + L2) ? L1 : (M + L2);
        float r = 0.f, i = 0.f;
        sum_m1<L1, L2, L, M, LO1, HI1>(A, Bv, r, i);
        acc[M + L] = make_float2(r, i);
        per_m<L1, L2, L, M + 1>(A, Bv, acc);
    }
}

// compute + immediately store one output L, then recurse to L+1
template <int L1, int L2, int L>
__device__ __forceinline__ void do_L(const float2* A, const float2* Bv,
                                     float* stage, float* outb, int lane, int t1) {
    constexpr int HI = (L1 + L2 < LMAXV) ? (L1 + L2) : LMAXV;
    if constexpr (L <= HI) {
        constexpr int TW = 2 * L + 1;
        float2 acc[TW];
        per_m<L1, L2, L, -L>(A, Bv, acc);

        // stage: lane t2 owns TW float2s, layout = exact gmem tile layout
        float2* st2 = (float2*)stage;
#pragma unroll
        for (int m = 0; m < TW; ++m) st2[lane * TW + m] = acc[m];
        __syncwarp();

        constexpr int OB = out_base_f(L1, L2, L);
        float4* g4 = (float4*)(outb + OB + t1 * 32 * 2 * TW);
        const float4* s4 = (const float4*)stage;
        constexpr int N4 = 16 * TW;   // 32 lanes * TW * 2 floats / 4
#pragma unroll
        for (int j = lane; j < N4; j += 32) g4[j] = s4[j];
        __syncwarp();

        do_L<L1, L2, L + 1>(A, Bv, stage, outb, lane, t1);
    }
}

// ---------------- per-pair block body ----------------

template <int L1, int L2>
__device__ __forceinline__ void block_work(const float* __restrict__ fs,
                                           float* __restrict__ out,
                                           float* s1, float* s2, float* stage,
                                           int q, int b) {
    const int tid = threadIdx.x;
    const int warp = tid >> 5;
    const int lane = tid & 31;
    constexpr int LO = (L1 > L2) ? (L1 - L2) : (L2 - L1);

    // stage input fragments (each is 32*(2l+1) float2, contiguous in gmem)
    {
        const float4* i1 = (const float4*)(fs + (size_t)b * 2304 + 64 * L1 * L1);
        const float4* i2 = (const float4*)(fs + (size_t)b * 2304 + 64 * L2 * L2);
        constexpr int N1 = 16 * (2 * L1 + 1);
        constexpr int N2 = 16 * (2 * L2 + 1);
#pragma unroll
        for (int j = tid; j < N1; j += 128) ((float4*)s1)[j] = i1[j];
#pragma unroll
        for (int j = tid; j < N2; j += 128) ((float4*)s2)[j] = i2[j];
    }
    __syncthreads();

    // Bv depends only on lane (t2): load once for both iterations
    float2 Bv[2 * L2 + 1];
    {
        const float2* bv = (const float2*)s2 + lane * (2 * L2 + 1);
#pragma unroll
        for (int i = 0; i < 2 * L2 + 1; ++i) Bv[i] = bv[i];
    }

    float* outb = out + (size_t)b * ROWF;
    float* wstage = stage + warp * 704;

#pragma unroll 1
    for (int iter = 0; iter < 2; ++iter) {
        const int t1 = q * 8 + iter * 4 + warp;

        float2 A[2 * L1 + 1];
        {
            const float2* av = (const float2*)s1 + t1 * (2 * L1 + 1);
#pragma unroll
            for (int i = 0; i < 2 * L1 + 1; ++i) A[i] = av[i];
        }

        do_L<L1, L2, LO>(A, Bv, wstage, outb, lane, t1);
    }
}

// ---------------- kernel ----------------

// heavy-first pair schedule: p = l1*6+l2, sorted by (2l1+1)(2l2+1) descending
__device__ const int PAIR_ORDER[36] = {
    35, 29, 34, 28, 23, 33, 22, 27, 32, 17, 21, 26,
    16, 15, 20, 31, 11, 25, 10, 14, 19,  9,  8, 13,
    30,  5, 24,  4,  7, 18,  3,  2, 12,  1,  6,  0
};

__global__ void __launch_bounds__(128, 6)
cg_sparse_kernel(const float* __restrict__ fs, float* __restrict__ out) {
    __shared__ __align__(16) float s1[704];
    __shared__ __align__(16) float s2[704];
    __shared__ __align__(16) float stage[4 * 704];

    const int bx = blockIdx.x;
    const int q = bx & 3;
    const int b = (bx >> 2) & 31;
    const int p = PAIR_ORDER[bx >> 7];   // heavy pairs launch first

#define PCASE(P, A_, B_) case P: block_work<A_, B_>(fs, out, s1, s2, stage, q, b); break;
    switch (p) {
        PCASE(0, 0, 0)  PCASE(1, 0, 1)  PCASE(2, 0, 2)  PCASE(3, 0, 3)  PCASE(4, 0, 4)  PCASE(5, 0, 5)
        PCASE(6, 1, 0)  PCASE(7, 1, 1)  PCASE(8, 1, 2)  PCASE(9, 1, 3)  PCASE(10, 1, 4) PCASE(11, 1, 5)
        PCASE(12, 2, 0) PCASE(13, 2, 1) PCASE(14, 2, 2) PCASE(15, 2, 3) PCASE(16, 2, 4) PCASE(17, 2, 5)
        PCASE(18, 3, 0) PCASE(19, 3, 1) PCASE(20, 3, 2) PCASE(21, 3, 3) PCASE(22, 3, 4) PCASE(23, 3, 5)
        PCASE(24, 4, 0) PCASE(25, 4, 1) PCASE(26, 4, 2) PCASE(27, 4, 3) PCASE(28, 4, 4) PCASE(29, 4, 5)
        PCASE(30, 5, 0) PCASE(31, 5, 1) PCASE(32, 5, 2) PCASE(33, 5, 3) PCASE(34, 5, 4) PCASE(35, 5, 5)
        default: break;
    }
#undef PCASE
}

extern "C" void kernel_launch(void* const* d_in, const int* in_sizes, int n_in,
                              void* d_out, int out_size) {
    const float* fs = (const float*)d_in[0];
    float* out = (float*)d_out;
    cg_sparse_kernel<<<NBLOCKS, 128>>>(fs, out);
}